// round 5
// baseline (speedup 1.0000x reference)
#include <cuda_runtime.h>
#include <math.h>
#include <stdint.h>

// ---------------------------------------------------------------------------
// Problem constants
// ---------------------------------------------------------------------------
#define BATCH      2048
#define TOKENS     8
#define MROWS      (BATCH * TOKENS)       // 16384
#define DIMT       1024
#define HIDT       4096
#define OUTT       1024
#define NHEADS     16
#define HEADD      64
#define ATT_SCALE  0.125f
#define LN_EPS     1e-5f

// ---------------------------------------------------------------------------
// Scratch (device globals)
// ---------------------------------------------------------------------------
__device__ float g_Q[(long)MROWS * DIMT];
__device__ float g_K[(long)MROWS * DIMT];
__device__ float g_V[(long)MROWS * HIDT];
__device__ float g_A[(long)MROWS * HIDT];

// ---------------------------------------------------------------------------
// Helpers
// ---------------------------------------------------------------------------
__device__ __forceinline__ uint32_t smem_u32(const void* p) {
    uint32_t a;
    asm("{ .reg .u64 t; cvta.to.shared.u64 t, %1; cvt.u32.u64 %0, t; }" : "=r"(a) : "l"(p));
    return a;
}
__device__ __forceinline__ void cp_async16(uint32_t dst, const void* src) {
    asm volatile("cp.async.cg.shared.global [%0], [%1], 16;" :: "r"(dst), "l"(src));
}
__device__ __forceinline__ uint32_t f2tf32(float f) {
    uint32_t t;
    asm("cvt.rna.tf32.f32 %0, %1;" : "=r"(t) : "f"(f));
    return t;
}
__device__ __forceinline__ void mma_tf32(float* d, const uint32_t* a, const uint32_t* b) {
    asm volatile("mma.sync.aligned.m16n8k8.row.col.f32.tf32.tf32.f32 "
        "{%0,%1,%2,%3}, {%4,%5,%6,%7}, {%8,%9}, {%0,%1,%2,%3};"
        : "+f"(d[0]), "+f"(d[1]), "+f"(d[2]), "+f"(d[3])
        : "r"(a[0]), "r"(a[1]), "r"(a[2]), "r"(a[3]), "r"(b[0]), "r"(b[1]));
}

// ---------------------------------------------------------------------------
// tf32 mma.sync GEMM: C[M,N] = A[M,K] @ W[K,N] + bias[N]
// CTA tile 128x256, BK=32, 8 warps (2x4 grid of 64x64 warp tiles),
// 4-stage cp.async pipeline, single __syncthreads per k-tile.
// SMEM per stage: A[128][36] + B[32][264] floats (both conflict-free).
// ---------------------------------------------------------------------------
#define GBM 128
#define GBN 256
#define KC  32
#define A_STRIDE 36
#define B_STRIDE 264
#define A_ST_FLOATS (GBM * A_STRIDE)                 // 4608
#define B_ST_FLOATS (KC * B_STRIDE)                  // 8448
#define STAGE_FLOATS (A_ST_FLOATS + B_ST_FLOATS)     // 13056
#define STAGE_BYTES (STAGE_FLOATS * 4)               // 52224
#define GEMM_SMEM (4 * STAGE_BYTES)                  // 208896

__global__ __launch_bounds__(256, 1)
void gemm_tc(const float* __restrict__ A, const float* __restrict__ W,
             const float* __restrict__ bias, float* __restrict__ C,
             int N, int K)
{
    extern __shared__ __align__(16) float smf[];
    const int tid  = threadIdx.x;
    const int wid  = tid >> 5;
    const int lane = tid & 31;
    const int lr = lane >> 2;       // 0..7
    const int lc = lane & 3;        // 0..3
    const int wm = (wid >> 2) * 64; // 0 | 64
    const int wn = (wid & 3) * 64;  // 0,64,128,192
    const long m0 = (long)blockIdx.y * GBM;
    const long n0 = (long)blockIdx.x * GBN;
    const int NK = K / KC;

    const uint32_t sbase = smem_u32(smf);

    auto load_stage = [&](int s, int kt) {
        const uint32_t abase = sbase + s * STAGE_BYTES;
        const uint32_t bbase = abase + A_ST_FLOATS * 4;
        const float* ag = A + m0 * K + (long)kt * KC;
        const float* bg = W + (long)kt * KC * N + n0;
        #pragma unroll
        for (int i = 0; i < 4; i++) {            // A: 128 rows x 8 float4
            const int u = tid + i * 256, r = u >> 3, c = u & 7;
            cp_async16(abase + r * (A_STRIDE * 4) + c * 16, ag + (long)r * K + c * 4);
        }
        #pragma unroll
        for (int i = 0; i < 8; i++) {            // B: 32 rows x 64 float4
            const int u = tid + i * 256, r = u >> 6, c = u & 63;
            cp_async16(bbase + r * (B_STRIDE * 4) + c * 16, bg + (long)r * N + c * 4);
        }
        asm volatile("cp.async.commit_group;" ::: "memory");
    };

    float d[4][8][4];
    #pragma unroll
    for (int mi = 0; mi < 4; mi++)
        #pragma unroll
        for (int ni = 0; ni < 8; ni++)
            #pragma unroll
            for (int r = 0; r < 4; r++) d[mi][ni][r] = 0.0f;

    load_stage(0, 0);
    load_stage(1, 1);
    load_stage(2, 2);

    for (int kt = 0; kt < NK; kt++) {
        const int s = kt & 3;
        asm volatile("cp.async.wait_group 2;" ::: "memory");
        __syncthreads();

        // issue next stage's loads first so the DMA overlaps the MMA burst;
        // target stage (kt+3)&3 == (kt-1)&3 was last READ in iteration kt-1,
        // and the barrier above guarantees every warp finished that compute.
        if (kt + 3 < NK) load_stage((kt + 3) & 3, kt + 3);
        else             asm volatile("cp.async.commit_group;" ::: "memory");

        const float* As = smf + s * STAGE_FLOATS;
        const float* Bs = As + A_ST_FLOATS;
        #pragma unroll
        for (int k0 = 0; k0 < KC; k0 += 8) {
            uint32_t af[4][4], bf[8][2];
            #pragma unroll
            for (int mi = 0; mi < 4; mi++) {
                const int r = wm + mi * 16 + lr;
                af[mi][0] = f2tf32(As[r * A_STRIDE + k0 + lc]);
                af[mi][1] = f2tf32(As[(r + 8) * A_STRIDE + k0 + lc]);
                af[mi][2] = f2tf32(As[r * A_STRIDE + k0 + lc + 4]);
                af[mi][3] = f2tf32(As[(r + 8) * A_STRIDE + k0 + lc + 4]);
            }
            #pragma unroll
            for (int ni = 0; ni < 8; ni++) {
                const int cn = wn + ni * 8 + lr;
                bf[ni][0] = f2tf32(Bs[(k0 + lc) * B_STRIDE + cn]);
                bf[ni][1] = f2tf32(Bs[(k0 + lc + 4) * B_STRIDE + cn]);
            }
            #pragma unroll
            for (int mi = 0; mi < 4; mi++)
                #pragma unroll
                for (int ni = 0; ni < 8; ni++)
                    mma_tf32(d[mi][ni], af[mi], bf[ni]);
        }
    }

    // Epilogue: bias add + store
    #pragma unroll
    for (int mi = 0; mi < 4; mi++) {
        const long r0 = m0 + wm + mi * 16 + lr;
        #pragma unroll
        for (int ni = 0; ni < 8; ni++) {
            const int c0 = (int)n0 + wn + ni * 8 + 2 * lc;
            const float b0 = bias[c0], b1 = bias[c0 + 1];
            float2 v0 = make_float2(d[mi][ni][0] + b0, d[mi][ni][1] + b1);
            float2 v1 = make_float2(d[mi][ni][2] + b0, d[mi][ni][3] + b1);
            *(float2*)&C[r0 * N + c0] = v0;
            *(float2*)&C[(r0 + 8) * N + c0] = v1;
        }
    }
}

// ---------------------------------------------------------------------------
// Fused attention + talking heads + softmax + attn@V + LayerNorm + swish.
// One block per batch element, 1024 threads; each thread owns 4 consecutive
// columns of HIDT (c = 4*tid), all within one head.
// ---------------------------------------------------------------------------
#define QK_STRIDE 1028    // pad to kill 8-way bank conflicts in score phase

__global__ __launch_bounds__(1024, 1)
void attn_ln_kernel(const float* __restrict__ Q, const float* __restrict__ Km,
                    const float* __restrict__ V,
                    const float* __restrict__ Wl, const float* __restrict__ bl,
                    const float* __restrict__ Ww, const float* __restrict__ bw,
                    const float* __restrict__ gamma, const float* __restrict__ beta,
                    float* __restrict__ Aout)
{
    extern __shared__ float dyn[];
    float* q_s = dyn;                        // 8 * 1028
    float* k_s = dyn + TOKENS * QK_STRIDE;   // 8 * 1028

    __shared__ float s_s[NHEADS][TOKENS][TOKENS];
    __shared__ float t_s[NHEADS][TOKENS][TOKENS];
    __shared__ float u_s[NHEADS][TOKENS][TOKENS];
    __shared__ float wl_s[256], ww_s[256], bl_s[16], bw_s[16];
    __shared__ float red[TOKENS][32];
    __shared__ float mean_s[TOKENS], rstd_s[TOKENS];

    const int b    = blockIdx.x;
    const int tid  = threadIdx.x;
    const int lane = tid & 31;
    const int wrp  = tid >> 5;
    const long rowbase = (long)b * TOKENS;

    {
        const long base = rowbase * DIMT;
        for (int i = tid; i < TOKENS * DIMT; i += 1024) {
            const int row = i >> 10, t = i & 1023;
            q_s[row * QK_STRIDE + t] = Q[base + i];
            k_s[row * QK_STRIDE + t] = Km[base + i];
        }
        if (tid < 256) { wl_s[tid] = Wl[tid]; ww_s[tid] = Ww[tid]; }
        else if (tid < 272) { bl_s[tid - 256] = bl[tid - 256]; }
        else if (tid < 288) { bw_s[tid - 272] = bw[tid - 272]; }
    }
    __syncthreads();

    // scores: one (h,n,m) per thread
    {
        const int h = tid >> 6, n = (tid >> 3) & 7, m = tid & 7;
        const float* qp = q_s + n * QK_STRIDE + h * HEADD;
        const float* kp = k_s + m * QK_STRIDE + h * HEADD;
        float dd = 0.0f;
        #pragma unroll
        for (int t = 0; t < HEADD; t++) dd += qp[t] * kp[t];
        s_s[h][n][m] = dd * ATT_SCALE;
    }
    __syncthreads();

    // talking-heads mix #1
    {
        const int g = tid >> 6, n = (tid >> 3) & 7, m = tid & 7;
        float acc = bl_s[g];
        #pragma unroll
        for (int h = 0; h < NHEADS; h++) acc += s_s[h][n][m] * wl_s[h * 16 + g];
        t_s[g][n][m] = acc;
    }
    __syncthreads();

    // softmax over m
    if (tid < 128) {
        const int g = tid >> 3, n = tid & 7;
        float mx = t_s[g][n][0];
        #pragma unroll
        for (int m = 1; m < TOKENS; m++) mx = fmaxf(mx, t_s[g][n][m]);
        float e[TOKENS], sum = 0.0f;
        #pragma unroll
        for (int m = 0; m < TOKENS; m++) { e[m] = expf(t_s[g][n][m] - mx); sum += e[m]; }
        const float inv = 1.0f / sum;
        #pragma unroll
        for (int m = 0; m < TOKENS; m++) t_s[g][n][m] = e[m] * inv;
    }
    __syncthreads();

    // talking-heads mix #2
    {
        const int g = tid >> 6, n = (tid >> 3) & 7, m = tid & 7;
        float acc = bw_s[g];
        #pragma unroll
        for (int h = 0; h < NHEADS; h++) acc += t_s[h][n][m] * ww_s[h * 16 + g];
        u_s[g][n][m] = acc;
    }
    __syncthreads();

    // o[n][c..c+3], c = 4*tid, head hh = tid >> 6 (constant within warp -> broadcast LDS)
    const int c0 = tid * 4;
    const int hh = tid >> 6;
    float4 acc4[TOKENS];
    #pragma unroll
    for (int n = 0; n < TOKENS; n++) acc4[n] = make_float4(0.f, 0.f, 0.f, 0.f);

    const float* Vb = V + rowbase * HIDT;
    #pragma unroll
    for (int m = 0; m < TOKENS; m++) {
        const float4 v4 = *(const float4*)(Vb + (long)m * HIDT + c0);
        #pragma unroll
        for (int n = 0; n < TOKENS; n++) {
            const float u = u_s[hh][n][m];
            acc4[n].x += u * v4.x;
            acc4[n].y += u * v4.y;
            acc4[n].z += u * v4.z;
            acc4[n].w += u * v4.w;
        }
    }

    // LayerNorm: mean via warp shuffle + 32-partial tree
    #pragma unroll
    for (int n = 0; n < TOKENS; n++) {
        float p = acc4[n].x + acc4[n].y + acc4[n].z + acc4[n].w;
        #pragma unroll
        for (int o = 16; o > 0; o >>= 1) p += __shfl_xor_sync(0xFFFFFFFF, p, o);
        if (lane == 0) red[n][wrp] = p;
    }
    __syncthreads();
    if (tid < TOKENS) {
        float s = 0.0f;
        #pragma unroll
        for (int w = 0; w < 32; w++) s += red[tid][w];
        mean_s[tid] = s * (1.0f / HIDT);
    }
    __syncthreads();
    // variance
    #pragma unroll
    for (int n = 0; n < TOKENS; n++) {
        const float mu = mean_s[n];
        const float dx = acc4[n].x - mu, dy = acc4[n].y - mu;
        const float dz = acc4[n].z - mu, dw = acc4[n].w - mu;
        float p = dx * dx + dy * dy + dz * dz + dw * dw;
        #pragma unroll
        for (int o = 16; o > 0; o >>= 1) p += __shfl_xor_sync(0xFFFFFFFF, p, o);
        if (lane == 0) red[n][wrp] = p;
    }
    __syncthreads();
    if (tid < TOKENS) {
        float s = 0.0f;
        #pragma unroll
        for (int w = 0; w < 32; w++) s += red[tid][w];
        rstd_s[tid] = rsqrtf(s * (1.0f / HIDT) + LN_EPS);
    }
    __syncthreads();

    // normalize + swish + store (gamma/beta hoisted: fixed columns per thread)
    const float4 g4 = *(const float4*)(gamma + c0);
    const float4 b4 = *(const float4*)(beta + c0);
    #pragma unroll
    for (int n = 0; n < TOKENS; n++) {
        const float mu = mean_s[n];
        const float rs = rstd_s[n];
        float4 y;
        y.x = (acc4[n].x - mu) * rs * g4.x + b4.x;
        y.y = (acc4[n].y - mu) * rs * g4.y + b4.y;
        y.z = (acc4[n].z - mu) * rs * g4.z + b4.z;
        y.w = (acc4[n].w - mu) * rs * g4.w + b4.w;
        y.x = y.x / (1.0f + expf(-y.x));
        y.y = y.y / (1.0f + expf(-y.y));
        y.z = y.z / (1.0f + expf(-y.z));
        y.w = y.w / (1.0f + expf(-y.w));
        *(float4*)(Aout + (rowbase + n) * HIDT + c0) = y;
    }
}

#define ATTN_SMEM (2 * TOKENS * QK_STRIDE * 4)   // 65792

// ---------------------------------------------------------------------------
// Launch
// ---------------------------------------------------------------------------
extern "C" void kernel_launch(void* const* d_in, const int* in_sizes, int n_in,
                              void* d_out, int out_size)
{
    const float* x     = (const float*)d_in[0];
    const float* Wq    = (const float*)d_in[1];
    const float* bq    = (const float*)d_in[2];
    const float* Wk    = (const float*)d_in[3];
    const float* bk    = (const float*)d_in[4];
    const float* Wv    = (const float*)d_in[5];
    const float* bv    = (const float*)d_in[6];
    const float* Wl    = (const float*)d_in[7];
    const float* bl    = (const float*)d_in[8];
    const float* Ww    = (const float*)d_in[9];
    const float* bw    = (const float*)d_in[10];
    const float* gamma = (const float*)d_in[11];
    const float* beta  = (const float*)d_in[12];
    const float* Wp    = (const float*)d_in[13];
    const float* bp    = (const float*)d_in[14];
    float* out = (float*)d_out;

    float *qb, *kb, *vb, *ab;
    cudaGetSymbolAddress((void**)&qb, g_Q);
    cudaGetSymbolAddress((void**)&kb, g_K);
    cudaGetSymbolAddress((void**)&vb, g_V);
    cudaGetSymbolAddress((void**)&ab, g_A);

    cudaFuncSetAttribute(gemm_tc, cudaFuncAttributeMaxDynamicSharedMemorySize, GEMM_SMEM);
    cudaFuncSetAttribute(attn_ln_kernel, cudaFuncAttributeMaxDynamicSharedMemorySize, ATTN_SMEM);

    gemm_tc<<<dim3(DIMT / GBN, MROWS / GBM), 256, GEMM_SMEM>>>(x, Wq, bq, qb, DIMT, DIMT);
    gemm_tc<<<dim3(DIMT / GBN, MROWS / GBM), 256, GEMM_SMEM>>>(x, Wk, bk, kb, DIMT, DIMT);
    gemm_tc<<<dim3(HIDT / GBN, MROWS / GBM), 256, GEMM_SMEM>>>(x, Wv, bv, vb, HIDT, DIMT);

    attn_ln_kernel<<<BATCH, 1024, ATTN_SMEM>>>(qb, kb, vb, Wl, bl, Ww, bw, gamma, beta, ab);

    gemm_tc<<<dim3(OUTT / GBN, MROWS / GBM), 256, GEMM_SMEM>>>(ab, Wp, bp, out, OUTT, HIDT);
}

// round 7
// speedup vs baseline: 1.1442x; 1.1442x over previous
#include <cuda_runtime.h>
#include <math.h>
#include <stdint.h>

// ---------------------------------------------------------------------------
// Problem constants
// ---------------------------------------------------------------------------
#define BATCH      2048
#define TOKENS     8
#define MROWS      (BATCH * TOKENS)       // 16384
#define DIMT       1024
#define HIDT       4096
#define OUTT       1024
#define NHEADS     16
#define HEADD      64
#define ATT_SCALE  0.125f
#define LN_EPS     1e-5f

// ---------------------------------------------------------------------------
// Scratch (device globals)
// ---------------------------------------------------------------------------
__device__ float g_Q[(long)MROWS * DIMT];
__device__ float g_K[(long)MROWS * DIMT];
__device__ float g_V[(long)MROWS * HIDT];
__device__ float g_A[(long)MROWS * HIDT];     // tf32-rounded activations
__device__ float g_X[(long)MROWS * DIMT];     // tf32-rounded x
__device__ float g_Wq[(long)DIMT * DIMT];
__device__ float g_Wk[(long)DIMT * DIMT];
__device__ float g_Wv[(long)DIMT * HIDT];
__device__ float g_Wp[(long)HIDT * OUTT];

// ---------------------------------------------------------------------------
// Helpers
// ---------------------------------------------------------------------------
__device__ __forceinline__ uint32_t smem_u32(const void* p) {
    uint32_t a;
    asm("{ .reg .u64 t; cvta.to.shared.u64 t, %1; cvt.u32.u64 %0, t; }" : "=r"(a) : "l"(p));
    return a;
}
__device__ __forceinline__ void cp_async16(uint32_t dst, const void* src) {
    asm volatile("cp.async.cg.shared.global [%0], [%1], 16;" :: "r"(dst), "l"(src));
}
__device__ __forceinline__ uint32_t f2tf32(float f) {
    uint32_t t;
    asm("cvt.rna.tf32.f32 %0, %1;" : "=r"(t) : "f"(f));
    return t;
}
__device__ __forceinline__ void mma_tf32(float* d, const uint32_t* a, const uint32_t* b) {
    asm volatile("mma.sync.aligned.m16n8k8.row.col.f32.tf32.tf32.f32 "
        "{%0,%1,%2,%3}, {%4,%5,%6,%7}, {%8,%9}, {%0,%1,%2,%3};"
        : "+f"(d[0]), "+f"(d[1]), "+f"(d[2]), "+f"(d[3])
        : "r"(a[0]), "r"(a[1]), "r"(a[2]), "r"(a[3]), "r"(b[0]), "r"(b[1]));
}

// ---------------------------------------------------------------------------
// Elementwise tf32 rounding: out[i] = round_tf32(in[i]) (stored as fp32 bits)
// ---------------------------------------------------------------------------
__global__ __launch_bounds__(256)
void round_tf32_kernel(const float* __restrict__ in, float* __restrict__ out, long n4)
{
    const long i = (long)blockIdx.x * 256 + threadIdx.x;
    if (i < n4) {
        float4 v = ((const float4*)in)[i];
        v.x = __uint_as_float(f2tf32(v.x));
        v.y = __uint_as_float(f2tf32(v.y));
        v.z = __uint_as_float(f2tf32(v.z));
        v.w = __uint_as_float(f2tf32(v.w));
        ((float4*)out)[i] = v;
    }
}

// ---------------------------------------------------------------------------
// tf32 mma.sync GEMM body (inputs pre-rounded to tf32 -> no cvt in loop).
// CTA tile 128x128, BK=32, 8 warps (2x4 grid of 64x32 warp tiles),
// 3-stage cp.async pipeline, 2 CTAs/SM, ONE __syncthreads per k-tile.
// SMEM per stage: A[128][36] + B[32][136] floats (conflict-free).
// ---------------------------------------------------------------------------
#define GBM 128
#define GBN 128
#define KC  32
#define A_STRIDE 36
#define B_STRIDE 136
#define A_ST_FLOATS (GBM * A_STRIDE)                 // 4608
#define STAGE_FLOATS (A_ST_FLOATS + KC * B_STRIDE)   // 8960
#define STAGE_BYTES (STAGE_FLOATS * 4)               // 35840
#define GEMM_SMEM (3 * STAGE_BYTES)                  // 107520

__device__ __forceinline__
void gemm_body(const float* __restrict__ A, const float* __restrict__ W,
               const float* __restrict__ bias, float* __restrict__ C,
               int N, int K, long m0, long n0, float* smf)
{
    const int tid  = threadIdx.x;
    const int wid  = tid >> 5;
    const int lane = tid & 31;
    const int lr = lane >> 2;       // 0..7
    const int lc = lane & 3;        // 0..3
    const int wm = (wid >> 2) * 64; // 0 | 64
    const int wn = (wid & 3) * 32;  // 0,32,64,96
    const int NK = K / KC;

    const uint32_t sbase = smem_u32(smf);

    auto load_stage = [&](int s, int kt) {
        const uint32_t abase = sbase + s * STAGE_BYTES;
        const uint32_t bbase = abase + A_ST_FLOATS * 4;
        const float* ag = A + m0 * K + (long)kt * KC;
        const float* bg = W + (long)kt * KC * N + n0;
        #pragma unroll
        for (int i = 0; i < 4; i++) {            // A: 128 rows x 8 float4
            const int u = tid + i * 256, r = u >> 3, c = u & 7;
            cp_async16(abase + r * (A_STRIDE * 4) + c * 16, ag + (long)r * K + c * 4);
        }
        #pragma unroll
        for (int i = 0; i < 4; i++) {            // B: 32 rows x 32 float4
            const int u = tid + i * 256, r = u >> 5, c = u & 31;
            cp_async16(bbase + r * (B_STRIDE * 4) + c * 16, bg + (long)r * N + c * 4);
        }
        asm volatile("cp.async.commit_group;" ::: "memory");
    };

    float d[4][4][4];
    #pragma unroll
    for (int mi = 0; mi < 4; mi++)
        #pragma unroll
        for (int ni = 0; ni < 4; ni++)
            #pragma unroll
            for (int r = 0; r < 4; r++) d[mi][ni][r] = 0.0f;

    load_stage(0, 0);
    load_stage(1, 1);

    int s = 0;
    for (int kt = 0; kt < NK; kt++) {
        asm volatile("cp.async.wait_group 1;" ::: "memory");
        __syncthreads();

        // Hoist next loads before compute: target stage (s+2)%3 was last READ
        // in iteration kt-1; the barrier above fences that compute.
        if (kt + 2 < NK) load_stage((s + 2) % 3, kt + 2);
        else             asm volatile("cp.async.commit_group;" ::: "memory");

        const float* As = smf + s * STAGE_FLOATS;
        const float* Bs = As + A_ST_FLOATS;
        #pragma unroll
        for (int k0 = 0; k0 < KC; k0 += 8) {
            uint32_t af[4][4], bf[4][2];
            #pragma unroll
            for (int mi = 0; mi < 4; mi++) {
                const int r = wm + mi * 16 + lr;
                af[mi][0] = __float_as_uint(As[r * A_STRIDE + k0 + lc]);
                af[mi][1] = __float_as_uint(As[(r + 8) * A_STRIDE + k0 + lc]);
                af[mi][2] = __float_as_uint(As[r * A_STRIDE + k0 + lc + 4]);
                af[mi][3] = __float_as_uint(As[(r + 8) * A_STRIDE + k0 + lc + 4]);
            }
            #pragma unroll
            for (int ni = 0; ni < 4; ni++) {
                const int cn = wn + ni * 8 + lr;
                bf[ni][0] = __float_as_uint(Bs[(k0 + lc) * B_STRIDE + cn]);
                bf[ni][1] = __float_as_uint(Bs[(k0 + lc + 4) * B_STRIDE + cn]);
            }
            #pragma unroll
            for (int mi = 0; mi < 4; mi++)
                #pragma unroll
                for (int ni = 0; ni < 4; ni++)
                    mma_tf32(d[mi][ni], af[mi], bf[ni]);
        }
        s = (s + 1) % 3;
    }

    // Epilogue: bias add + store
    #pragma unroll
    for (int mi = 0; mi < 4; mi++) {
        const long r0 = m0 + wm + mi * 16 + lr;
        #pragma unroll
        for (int ni = 0; ni < 4; ni++) {
            const int c0 = (int)n0 + wn + ni * 8 + 2 * lc;
            const float b0 = bias[c0], b1 = bias[c0 + 1];
            float2 v0 = make_float2(d[mi][ni][0] + b0, d[mi][ni][1] + b1);
            float2 v1 = make_float2(d[mi][ni][2] + b0, d[mi][ni][3] + b1);
            *(float2*)&C[r0 * N + c0] = v0;
            *(float2*)&C[(r0 + 8) * N + c0] = v1;
        }
    }
}

// Fused Q/K/V projection: grid.x = 8 (Q) + 8 (K) + 32 (V) column tiles.
__global__ __launch_bounds__(256, 2)
void gemm_qkv(const float* __restrict__ X,
              const float* __restrict__ Wq, const float* __restrict__ bq, float* __restrict__ Qo,
              const float* __restrict__ Wk, const float* __restrict__ bk, float* __restrict__ Ko,
              const float* __restrict__ Wv, const float* __restrict__ bv, float* __restrict__ Vo)
{
    extern __shared__ __align__(16) float smf[];
    const int bx = blockIdx.x;
    const float *W, *bias;
    float* C;
    int N;
    long n0;
    if (bx < 8)       { W = Wq; bias = bq; C = Qo; N = DIMT; n0 = (long)bx * GBN; }
    else if (bx < 16) { W = Wk; bias = bk; C = Ko; N = DIMT; n0 = (long)(bx - 8) * GBN; }
    else              { W = Wv; bias = bv; C = Vo; N = HIDT; n0 = (long)(bx - 16) * GBN; }
    gemm_body(X, W, bias, C, N, DIMT, (long)blockIdx.y * GBM, n0, smf);
}

// Plain GEMM for the output projection.
__global__ __launch_bounds__(256, 2)
void gemm_tc(const float* __restrict__ A, const float* __restrict__ W,
             const float* __restrict__ bias, float* __restrict__ C,
             int N, int K)
{
    extern __shared__ __align__(16) float smf[];
    gemm_body(A, W, bias, C, N, K,
              (long)blockIdx.y * GBM, (long)blockIdx.x * GBN, smf);
}

// ---------------------------------------------------------------------------
// Fused attention + talking heads + softmax + attn@V + LayerNorm + swish.
// One block per batch element, 1024 threads; each thread owns 4 consecutive
// columns of HIDT (c = 4*tid). Output rounded to tf32 for the P GEMM.
// ---------------------------------------------------------------------------
#define QK_STRIDE 1028

__global__ __launch_bounds__(1024, 1)
void attn_ln_kernel(const float* __restrict__ Q, const float* __restrict__ Km,
                    const float* __restrict__ V,
                    const float* __restrict__ Wl, const float* __restrict__ bl,
                    const float* __restrict__ Ww, const float* __restrict__ bw,
                    const float* __restrict__ gamma, const float* __restrict__ beta,
                    float* __restrict__ Aout)
{
    extern __shared__ float dyn[];
    float* q_s = dyn;                        // 8 * 1028
    float* k_s = dyn + TOKENS * QK_STRIDE;   // 8 * 1028

    __shared__ float s_s[NHEADS][TOKENS][TOKENS];
    __shared__ float t_s[NHEADS][TOKENS][TOKENS];
    __shared__ float u_s[NHEADS][TOKENS][TOKENS];
    __shared__ float wl_s[256], ww_s[256], bl_s[16], bw_s[16];
    __shared__ float red[TOKENS][32];
    __shared__ float mean_s[TOKENS], rstd_s[TOKENS];

    const int b    = blockIdx.x;
    const int tid  = threadIdx.x;
    const int lane = tid & 31;
    const int wrp  = tid >> 5;
    const long rowbase = (long)b * TOKENS;

    {
        const long base = rowbase * DIMT;
        for (int i = tid; i < TOKENS * DIMT; i += 1024) {
            const int row = i >> 10, t = i & 1023;
            q_s[row * QK_STRIDE + t] = Q[base + i];
            k_s[row * QK_STRIDE + t] = Km[base + i];
        }
        if (tid < 256) { wl_s[tid] = Wl[tid]; ww_s[tid] = Ww[tid]; }
        else if (tid < 272) { bl_s[tid - 256] = bl[tid - 256]; }
        else if (tid < 288) { bw_s[tid - 272] = bw[tid - 272]; }
    }
    __syncthreads();

    // scores: one (h,n,m) per thread
    {
        const int h = tid >> 6, n = (tid >> 3) & 7, m = tid & 7;
        const float* qp = q_s + n * QK_STRIDE + h * HEADD;
        const float* kp = k_s + m * QK_STRIDE + h * HEADD;
        float dd = 0.0f;
        #pragma unroll
        for (int t = 0; t < HEADD; t++) dd += qp[t] * kp[t];
        s_s[h][n][m] = dd * ATT_SCALE;
    }
    __syncthreads();

    // talking-heads mix #1
    {
        const int g = tid >> 6, n = (tid >> 3) & 7, m = tid & 7;
        float acc = bl_s[g];
        #pragma unroll
        for (int h = 0; h < NHEADS; h++) acc += s_s[h][n][m] * wl_s[h * 16 + g];
        t_s[g][n][m] = acc;
    }
    __syncthreads();

    // softmax over m
    if (tid < 128) {
        const int g = tid >> 3, n = tid & 7;
        float mx = t_s[g][n][0];
        #pragma unroll
        for (int m = 1; m < TOKENS; m++) mx = fmaxf(mx, t_s[g][n][m]);
        float e[TOKENS], sum = 0.0f;
        #pragma unroll
        for (int m = 0; m < TOKENS; m++) { e[m] = expf(t_s[g][n][m] - mx); sum += e[m]; }
        const float inv = 1.0f / sum;
        #pragma unroll
        for (int m = 0; m < TOKENS; m++) t_s[g][n][m] = e[m] * inv;
    }
    __syncthreads();

    // talking-heads mix #2
    {
        const int g = tid >> 6, n = (tid >> 3) & 7, m = tid & 7;
        float acc = bw_s[g];
        #pragma unroll
        for (int h = 0; h < NHEADS; h++) acc += t_s[h][n][m] * ww_s[h * 16 + g];
        u_s[g][n][m] = acc;
    }
    __syncthreads();

    // o[n][c..c+3], c = 4*tid, head hh = tid >> 6 (warp-uniform -> broadcast LDS)
    const int c0 = tid * 4;
    const int hh = tid >> 6;
    float4 acc4[TOKENS];
    #pragma unroll
    for (int n = 0; n < TOKENS; n++) acc4[n] = make_float4(0.f, 0.f, 0.f, 0.f);

    const float* Vb = V + rowbase * HIDT;
    #pragma unroll
    for (int m = 0; m < TOKENS; m++) {
        const float4 v4 = *(const float4*)(Vb + (long)m * HIDT + c0);
        #pragma unroll
        for (int n = 0; n < TOKENS; n++) {
            const float u = u_s[hh][n][m];
            acc4[n].x += u * v4.x;
            acc4[n].y += u * v4.y;
            acc4[n].z += u * v4.z;
            acc4[n].w += u * v4.w;
        }
    }

    // LayerNorm: mean via warp shuffle + 32-partial tree
    #pragma unroll
    for (int n = 0; n < TOKENS; n++) {
        float p = acc4[n].x + acc4[n].y + acc4[n].z + acc4[n].w;
        #pragma unroll
        for (int o = 16; o > 0; o >>= 1) p += __shfl_xor_sync(0xFFFFFFFF, p, o);
        if (lane == 0) red[n][wrp] = p;
    }
    __syncthreads();
    if (tid < TOKENS) {
        float s = 0.0f;
        #pragma unroll
        for (int w = 0; w < 32; w++) s += red[tid][w];
        mean_s[tid] = s * (1.0f / HIDT);
    }
    __syncthreads();
    // variance
    #pragma unroll
    for (int n = 0; n < TOKENS; n++) {
        const float mu = mean_s[n];
        const float dx = acc4[n].x - mu, dy = acc4[n].y - mu;
        const float dz = acc4[n].z - mu, dw = acc4[n].w - mu;
        float p = dx * dx + dy * dy + dz * dz + dw * dw;
        #pragma unroll
        for (int o = 16; o > 0; o >>= 1) p += __shfl_xor_sync(0xFFFFFFFF, p, o);
        if (lane == 0) red[n][wrp] = p;
    }
    __syncthreads();
    if (tid < TOKENS) {
        float s = 0.0f;
        #pragma unroll
        for (int w = 0; w < 32; w++) s += red[tid][w];
        rstd_s[tid] = rsqrtf(s * (1.0f / HIDT) + LN_EPS);
    }
    __syncthreads();

    // normalize + swish + tf32-round + store
    const float4 g4 = *(const float4*)(gamma + c0);
    const float4 b4 = *(const float4*)(beta + c0);
    #pragma unroll
    for (int n = 0; n < TOKENS; n++) {
        const float mu = mean_s[n];
        const float rs = rstd_s[n];
        float4 y;
        y.x = (acc4[n].x - mu) * rs * g4.x + b4.x;
        y.y = (acc4[n].y - mu) * rs * g4.y + b4.y;
        y.z = (acc4[n].z - mu) * rs * g4.z + b4.z;
        y.w = (acc4[n].w - mu) * rs * g4.w + b4.w;
        y.x = __uint_as_float(f2tf32(y.x / (1.0f + expf(-y.x))));
        y.y = __uint_as_float(f2tf32(y.y / (1.0f + expf(-y.y))));
        y.z = __uint_as_float(f2tf32(y.z / (1.0f + expf(-y.z))));
        y.w = __uint_as_float(f2tf32(y.w / (1.0f + expf(-y.w))));
        *(float4*)(Aout + (rowbase + n) * HIDT + c0) = y;
    }
}

#define ATTN_SMEM (2 * TOKENS * QK_STRIDE * 4)   // 65792

// ---------------------------------------------------------------------------
// Launch
// ---------------------------------------------------------------------------
extern "C" void kernel_launch(void* const* d_in, const int* in_sizes, int n_in,
                              void* d_out, int out_size)
{
    const float* x     = (const float*)d_in[0];
    const float* Wq    = (const float*)d_in[1];
    const float* bq    = (const float*)d_in[2];
    const float* Wk    = (const float*)d_in[3];
    const float* bk    = (const float*)d_in[4];
    const float* Wv    = (const float*)d_in[5];
    const float* bv    = (const float*)d_in[6];
    const float* Wl    = (const float*)d_in[7];
    const float* bl    = (const float*)d_in[8];
    const float* Ww    = (const float*)d_in[9];
    const float* bw    = (const float*)d_in[10];
    const float* gamma = (const float*)d_in[11];
    const float* beta  = (const float*)d_in[12];
    const float* Wp    = (const float*)d_in[13];
    const float* bp    = (const float*)d_in[14];
    float* out = (float*)d_out;

    float *qb, *kb, *vb, *ab, *xr, *wqr, *wkr, *wvr, *wpr;
    cudaGetSymbolAddress((void**)&qb, g_Q);
    cudaGetSymbolAddress((void**)&kb, g_K);
    cudaGetSymbolAddress((void**)&vb, g_V);
    cudaGetSymbolAddress((void**)&ab, g_A);
    cudaGetSymbolAddress((void**)&xr, g_X);
    cudaGetSymbolAddress((void**)&wqr, g_Wq);
    cudaGetSymbolAddress((void**)&wkr, g_Wk);
    cudaGetSymbolAddress((void**)&wvr, g_Wv);
    cudaGetSymbolAddress((void**)&wpr, g_Wp);

    cudaFuncSetAttribute(gemm_qkv, cudaFuncAttributeMaxDynamicSharedMemorySize, GEMM_SMEM);
    cudaFuncSetAttribute(gemm_tc, cudaFuncAttributeMaxDynamicSharedMemorySize, GEMM_SMEM);
    cudaFuncSetAttribute(attn_ln_kernel, cudaFuncAttributeMaxDynamicSharedMemorySize, ATTN_SMEM);

    // Pre-round GEMM inputs to tf32 (idempotent, same numerics as in-loop cvt)
    {
        const long nx = (long)MROWS * DIMT / 4;
        round_tf32_kernel<<<(unsigned)((nx + 255) / 256), 256>>>(x, xr, nx);
        const long nq = (long)DIMT * DIMT / 4;
        round_tf32_kernel<<<(unsigned)((nq + 255) / 256), 256>>>(Wq, wqr, nq);
        round_tf32_kernel<<<(unsigned)((nq + 255) / 256), 256>>>(Wk, wkr, nq);
        const long nv = (long)DIMT * HIDT / 4;
        round_tf32_kernel<<<(unsigned)((nv + 255) / 256), 256>>>(Wv, wvr, nv);
        const long np = (long)HIDT * OUTT / 4;
        round_tf32_kernel<<<(unsigned)((np + 255) / 256), 256>>>(Wp, wpr, np);
    }

    // Fused Q/K/V projection (x streamed once)
    gemm_qkv<<<dim3(48, MROWS / GBM), 256, GEMM_SMEM>>>(
        xr, wqr, bq, qb, wkr, bk, kb, wvr, bv, vb);

    // attention + talking heads + softmax + attn@V + LayerNorm + swish
    attn_ln_kernel<<<BATCH, 1024, ATTN_SMEM>>>(qb, kb, vb, Wl, bl, Ww, bw, gamma, beta, ab);

    // out = a @ Wp + bp
    gemm_tc<<<dim3(OUTT / GBN, MROWS / GBM), 256, GEMM_SMEM>>>(ab, wpr, bp, out, OUTT, HIDT);
}